// round 1
// baseline (speedup 1.0000x reference)
#include <cuda_runtime.h>
#include <cuda_bf16.h>
#include <math.h>

// Problem dims (fixed)
#define B   64
#define S   128
#define H   256
#define H2  512
#define H3  768
#define H4  1024
#define V   32000
#define T   32

// ------------------------- scratch (static device globals) -------------------------
__device__ float g_encp[B * S * H2];          // enc @ Ww.T + Wb   (16.8 MB)
__device__ float g_UwS[H2 * H];               // Uw[:, :H] + Uw[:, H:]
__device__ float g_qU[B * H2];                // h_f @ UwS.T + Ub
__device__ float g_ctx[B * H2];               // attention context
__device__ float g_xin[2 * B * H4];           // [ctx, emb, h_d] per direction
__device__ float g_Wcat[2 * H4 * H4];         // [Wih | Whh] per direction (8 MB)
__device__ float g_bcat[2 * H4];
__device__ float g_Gp[4 * 2 * B * H4];        // split-K partial gate sums (2 MB)
__device__ float g_h[2 * B * H];
__device__ float g_c[2 * B * H];
__device__ float g_out[B * H2];               // concat(hf, hb)
__device__ int   g_x[B];                      // greedy token feedback

__device__ __forceinline__ float warpsum(float v) {
    #pragma unroll
    for (int o = 16; o > 0; o >>= 1) v += __shfl_xor_sync(0xffffffffu, v, o);
    return v;
}
__device__ __forceinline__ float sigf(float x) { return 1.0f / (1.0f + expf(-x)); }

// ------------------------- one-time pack / init -------------------------
__global__ void pack_kernel(const float* __restrict__ Uw,
                            const float* __restrict__ Wih_f, const float* __restrict__ Whh_f,
                            const float* __restrict__ b_f,
                            const float* __restrict__ Wih_b, const float* __restrict__ Whh_b,
                            const float* __restrict__ b_b,
                            const float* __restrict__ h0, const float* __restrict__ c0) {
    const size_t NTOT = (size_t)2 * H4 * H4;  // 2,097,152
    for (size_t idx = (size_t)blockIdx.x * blockDim.x + threadIdx.x; idx < NTOT;
         idx += (size_t)gridDim.x * blockDim.x) {
        size_t d = idx >> 20;
        size_t r = (idx >> 10) & 1023;
        size_t k = idx & 1023;
        const float* Wih = d ? Wih_b : Wih_f;
        const float* Whh = d ? Whh_b : Whh_f;
        g_Wcat[idx] = (k < H3) ? Wih[r * H3 + k] : Whh[r * H + (k - H3)];

        if (idx < (size_t)H2 * H) {
            size_t j = idx >> 8, kk = idx & 255;
            g_UwS[idx] = Uw[j * H2 + kk] + Uw[j * H2 + H + kk];
        }
        if (idx < 2 * H4) g_bcat[idx] = (idx < H4) ? b_f[idx] : b_b[idx - H4];
        if (idx < 2 * B * H) { g_h[idx] = h0[idx]; g_c[idx] = c0[idx]; }
        if (idx < B) g_x[idx] = 0;
    }
}

// ------------------------- generic fp32 GEMM: C = A @ W.T + bias -------------------------
// A:[M,K] row-major, W:[N,K] row-major, C row stride ldC. All dims divide tile sizes.
// blockIdx.z batches (zA/zW/zB/zC strides). ksplit>1: blockIdx.y = k-slice (requires M<=64),
// each slice writes its partial into C + ks*zCk; bias added only in slice 0.
#define GBM 64
#define GBN 128
#define GBK 32
__global__ void __launch_bounds__(256) gemm_abt(
    const float* __restrict__ A, const float* __restrict__ W,
    const float* __restrict__ bias, float* __restrict__ C,
    int M, int N, int K, int ldC,
    size_t zA, size_t zW, size_t zB, size_t zC,
    int ksplit, size_t zCk) {
    A += (size_t)blockIdx.z * zA;
    W += (size_t)blockIdx.z * zW;
    bias += (size_t)blockIdx.z * zB;
    C += (size_t)blockIdx.z * zC;

    int mb, ks;
    if (ksplit > 1) { mb = 0; ks = blockIdx.y; } else { mb = blockIdx.y; ks = 0; }
    const int kLen = K / ksplit;
    const int kBegin = ks * kLen;
    C += (size_t)ks * zCk;

    __shared__ float As[GBK][GBM];
    __shared__ float Bs[GBK][GBN];

    const int tid = threadIdx.x;
    const int tx = tid & 15, ty = tid >> 4;     // 16 x 16 threads
    const int mBase = mb * GBM;
    const int nBase = blockIdx.x * GBN;

    float acc[4][8];
    #pragma unroll
    for (int i = 0; i < 4; i++)
        #pragma unroll
        for (int j = 0; j < 8; j++) acc[i][j] = 0.0f;

    for (int k0 = kBegin; k0 < kBegin + kLen; k0 += GBK) {
        // A tile: 64x32 = 512 float4 -> 2 per thread
        #pragma unroll
        for (int i = 0; i < 2; i++) {
            int f4 = tid + 256 * i;
            int r = f4 >> 3, kq = f4 & 7;
            float4 v = *reinterpret_cast<const float4*>(&A[(size_t)(mBase + r) * K + k0 + kq * 4]);
            As[kq * 4 + 0][r] = v.x; As[kq * 4 + 1][r] = v.y;
            As[kq * 4 + 2][r] = v.z; As[kq * 4 + 3][r] = v.w;
        }
        // B tile: 128x32 = 1024 float4 -> 4 per thread
        #pragma unroll
        for (int i = 0; i < 4; i++) {
            int f4 = tid + 256 * i;
            int r = f4 >> 3, kq = f4 & 7;
            float4 v = *reinterpret_cast<const float4*>(&W[(size_t)(nBase + r) * K + k0 + kq * 4]);
            Bs[kq * 4 + 0][r] = v.x; Bs[kq * 4 + 1][r] = v.y;
            Bs[kq * 4 + 2][r] = v.z; Bs[kq * 4 + 3][r] = v.w;
        }
        __syncthreads();
        #pragma unroll
        for (int k = 0; k < GBK; k++) {
            float4 a4 = *reinterpret_cast<const float4*>(&As[k][ty * 4]);
            float4 b0 = *reinterpret_cast<const float4*>(&Bs[k][tx * 8]);
            float4 b1 = *reinterpret_cast<const float4*>(&Bs[k][tx * 8 + 4]);
            float a[4] = {a4.x, a4.y, a4.z, a4.w};
            float b[8] = {b0.x, b0.y, b0.z, b0.w, b1.x, b1.y, b1.z, b1.w};
            #pragma unroll
            for (int i = 0; i < 4; i++)
                #pragma unroll
                for (int j = 0; j < 8; j++) acc[i][j] = fmaf(a[i], b[j], acc[i][j]);
        }
        __syncthreads();
    }

    #pragma unroll
    for (int i = 0; i < 4; i++) {
        size_t row = (size_t)(mBase + ty * 4 + i);
        #pragma unroll
        for (int j = 0; j < 8; j++) {
            int col = nBase + tx * 8 + j;
            float bj = (ks == 0) ? bias[col] : 0.0f;
            C[row * (size_t)ldC + col] = acc[i][j] + bj;
        }
    }
}

// ------------------------- attention -------------------------
// qU[b,j] = Ub[j] + sum_k h_f[b,k] * UwS[j,k]
__global__ void attn_qU_kernel(const float* __restrict__ Ub) {
    __shared__ float h_s[H];
    int b = blockIdx.x, tid = threadIdx.x;
    if (tid < H) h_s[tid] = g_h[(size_t)b * H + tid];   // forward dir (d=0)
    __syncthreads();
    int warp = tid >> 5, lane = tid & 31;
    for (int j = warp; j < H2; j += 8) {
        const float* u = g_UwS + (size_t)j * H;
        float s = 0.0f;
        #pragma unroll
        for (int k = lane; k < H; k += 32) s += u[k] * h_s[k];
        s = warpsum(s);
        if (lane == 0) g_qU[(size_t)b * H2 + j] = s + Ub[j];
    }
}

// per-batch fused: score = Vw . tanh(qU + enc_proj) + Vb; softmax; ctx = w @ enc
__global__ void __launch_bounds__(256) attn_kernel(const float* __restrict__ enc,
                                                   const float* __restrict__ Vw,
                                                   const float* __restrict__ Vb) {
    __shared__ float qs[H2], vs[H2], sc[S], rb[S];
    int b = blockIdx.x, tid = threadIdx.x;
    for (int j = tid; j < H2; j += 256) { qs[j] = g_qU[(size_t)b * H2 + j]; vs[j] = Vw[j]; }
    __syncthreads();
    int warp = tid >> 5, lane = tid & 31;
    float vb = Vb[0];
    for (int s = warp; s < S; s += 8) {
        const float* ep = g_encp + ((size_t)b * S + s) * H2;
        float acc = 0.0f;
        #pragma unroll
        for (int j = lane; j < H2; j += 32) acc += vs[j] * tanhf(qs[j] + ep[j]);
        acc = warpsum(acc);
        if (lane == 0) sc[s] = acc + vb;
    }
    __syncthreads();
    // softmax over S=128
    if (tid < S) rb[tid] = sc[tid];
    __syncthreads();
    for (int st = 64; st > 0; st >>= 1) {
        if (tid < st) rb[tid] = fmaxf(rb[tid], rb[tid + st]);
        __syncthreads();
    }
    float mx = rb[0];
    __syncthreads();
    if (tid < S) { float e = expf(sc[tid] - mx); sc[tid] = e; rb[tid] = e; }
    __syncthreads();
    for (int st = 64; st > 0; st >>= 1) {
        if (tid < st) rb[tid] += rb[tid + st];
        __syncthreads();
    }
    float inv = 1.0f / rb[0];
    __syncthreads();
    if (tid < S) sc[tid] *= inv;
    __syncthreads();
    // ctx[b,d] = sum_s w[s] * enc[b,s,d]
    for (int d = tid; d < H2; d += 256) {
        const float* eb = enc + (size_t)b * S * H2 + d;
        float acc = 0.0f;
        #pragma unroll 8
        for (int s = 0; s < S; s++) acc += sc[s] * eb[(size_t)s * H2];
        g_ctx[(size_t)b * H2 + d] = acc;
    }
}

// ------------------------- LSTM input gather -------------------------
__global__ void build_xin_kernel(const float* __restrict__ embt) {
    int idx = blockIdx.x * blockDim.x + threadIdx.x;   // < 2*64*1024
    if (idx >= 2 * B * H4) return;
    int d = idx >> 16;
    int b = (idx >> 10) & (B - 1);
    int k = idx & (H4 - 1);
    float v;
    if (k < H2)       v = g_ctx[b * H2 + k];
    else if (k < H3)  v = embt[(size_t)g_x[b] * H + (k - H2)];
    else              v = g_h[(d * B + b) * H + (k - H3)];
    g_xin[idx] = v;
}

// ------------------------- LSTM activation (sums split-K partials) -------------------------
__global__ void lstm_act_kernel() {
    int idx = blockIdx.x * blockDim.x + threadIdx.x;   // < 2*64*256
    if (idx >= 2 * B * H) return;
    int d = idx / (B * H);
    int b = (idx / H) % B;
    int k = idx % H;
    size_t base = ((size_t)d * B + b) * H4;
    float gi = 0, gf = 0, gg = 0, go = 0;
    #pragma unroll
    for (int s = 0; s < 4; s++) {
        const float* Gp = g_Gp + (size_t)s * 2 * B * H4 + base;
        gi += Gp[k]; gf += Gp[H + k]; gg += Gp[2 * H + k]; go += Gp[3 * H + k];
    }
    float c_old = g_c[idx];
    float c2 = sigf(gf) * c_old + sigf(gi) * tanhf(gg);
    float h2 = sigf(go) * tanhf(c2);
    g_c[idx] = c2;
    g_h[idx] = h2;
    g_out[(size_t)b * H2 + d * H + k] = h2;
}

// ------------------------- argmax (first-index tie-break, like jnp.argmax) -------------------------
__global__ void argmax_kernel(const float* __restrict__ yt) {
    int b = blockIdx.x, tid = threadIdx.x;
    const float* row = yt + (size_t)b * T * V;
    float best = -INFINITY; int bi = 0x7fffffff;
    for (int v = tid; v < V; v += 256) {
        float val = row[v];
        if (val > best) { best = val; bi = v; }   // strided ascending -> first-idx on ties
    }
    __shared__ float bv[256];
    __shared__ int   bx[256];
    bv[tid] = best; bx[tid] = bi;
    __syncthreads();
    for (int st = 128; st > 0; st >>= 1) {
        if (tid < st) {
            if (bv[tid + st] > bv[tid] ||
                (bv[tid + st] == bv[tid] && bx[tid + st] < bx[tid])) {
                bv[tid] = bv[tid + st]; bx[tid] = bx[tid + st];
            }
        }
        __syncthreads();
    }
    if (tid == 0) g_x[b] = bx[0];
}

// ------------------------- tail: hT, cT -------------------------
__global__ void tail_kernel(float* __restrict__ out) {
    int idx = blockIdx.x * blockDim.x + threadIdx.x;
    if (idx < 2 * B * H) {
        out[(size_t)B * T * V + idx] = g_h[idx];
        out[(size_t)B * T * V + 2 * B * H + idx] = g_c[idx];
    }
}

// ------------------------- host -------------------------
extern "C" void kernel_launch(void* const* d_in, const int* in_sizes, int n_in,
                              void* d_out, int out_size) {
    const float* enc   = (const float*)d_in[0];
    const float* h0    = (const float*)d_in[1];
    const float* c0    = (const float*)d_in[2];
    const float* Uw    = (const float*)d_in[3];
    const float* Ub    = (const float*)d_in[4];
    const float* Ww    = (const float*)d_in[5];
    const float* Wb    = (const float*)d_in[6];
    const float* Vw    = (const float*)d_in[7];
    const float* Vb    = (const float*)d_in[8];
    const float* Wih_f = (const float*)d_in[9];
    const float* Whh_f = (const float*)d_in[10];
    const float* b_f   = (const float*)d_in[11];
    const float* Wih_b = (const float*)d_in[12];
    const float* Whh_b = (const float*)d_in[13];
    const float* b_b   = (const float*)d_in[14];
    const float* Fw    = (const float*)d_in[15];
    const float* Fb    = (const float*)d_in[16];
    const float* embt  = (const float*)d_in[17];
    (void)in_sizes; (void)n_in;
    float* out = (float*)d_out;

    // one-time packing + state init
    pack_kernel<<<2048, 1024>>>(Uw, Wih_f, Whh_f, b_f, Wih_b, Whh_b, b_b, h0, c0);

    // enc_proj = enc @ Ww.T + Wb   (M=8192, N=512, K=512)
    {
        float* encp;  cudaGetSymbolAddress((void**)&encp, g_encp);
        gemm_abt<<<dim3(H2 / GBN, (B * S) / GBM, 1), 256>>>(
            enc, Ww, Wb, encp, B * S, H2, H2, H2, 0, 0, 0, 0, 1, 0);
    }

    float *xin, *Wcat, *bcat, *Gp, *outbuf;
    cudaGetSymbolAddress((void**)&xin,   g_xin);
    cudaGetSymbolAddress((void**)&Wcat,  g_Wcat);
    cudaGetSymbolAddress((void**)&bcat,  g_bcat);
    cudaGetSymbolAddress((void**)&Gp,    g_Gp);
    cudaGetSymbolAddress((void**)&outbuf, g_out);

    for (int t = 0; t < T; t++) {
        attn_qU_kernel<<<B, 256>>>(Ub);
        attn_kernel<<<B, 256>>>(enc, Vw, Vb);
        build_xin_kernel<<<(2 * B * H4) / 256, 256>>>(embt);
        // gates: xin_d @ Wcat_d.T + b_d, split-K x4, dirs via z
        gemm_abt<<<dim3(H4 / GBN, 4, 2), 256>>>(
            xin, Wcat, bcat, Gp, B, H4, H4, H4,
            (size_t)B * H4, (size_t)H4 * H4, (size_t)H4, (size_t)B * H4,
            4, (size_t)2 * B * H4);
        lstm_act_kernel<<<(2 * B * H) / 256, 256>>>();
        // logits: out @ Fw.T + Fb, written directly into ys[:, t, :]
        gemm_abt<<<dim3(V / GBN, 1, 1), 256>>>(
            outbuf, Fw, Fb, out + (size_t)t * V, B, V, H2, T * V,
            0, 0, 0, 0, 1, 0);
        argmax_kernel<<<B, 256>>>(out + (size_t)t * V);
    }

    if (out_size >= B * T * V + 4 * B * H)
        tail_kernel<<<(2 * B * H + 255) / 256, 256>>>(out);
}

// round 2
// speedup vs baseline: 1.4004x; 1.4004x over previous
#include <cuda_runtime.h>
#include <cuda_bf16.h>
#include <math.h>

// Problem dims (fixed)
#define B   64
#define S   128
#define H   256
#define H2  512
#define H3  768
#define H4  1024
#define V   32000
#define T   32

#define KSPLIT_G 8   // gates GEMM k-split

// ------------------------- scratch (static device globals) -------------------------
__device__ float g_encp[B * S * H2];          // enc @ Ww.T + Wb   (16.8 MB)
__device__ float g_UwS[H2 * H];               // Uw[:, :H] + Uw[:, H:]
__device__ float g_qU[B * H2];                // h_f @ UwS.T + Ub
__device__ float g_score[B * S];              // raw attention scores
__device__ float g_ctx[B * H2];               // attention context
__device__ float g_xin[2 * B * H4];           // [ctx, emb, h_d] per direction
__device__ float g_Wcat[2 * H4 * H4];         // [Wih | Whh] per direction (8 MB)
__device__ float g_bcat[2 * H4];
__device__ float g_Gp[KSPLIT_G * 2 * B * H4]; // split-K partial gate sums (4 MB)
__device__ float g_h[2 * B * H];
__device__ float g_c[2 * B * H];
__device__ float g_out[B * H2];               // concat(hf, hb)
__device__ int   g_x[B];                      // greedy token feedback

__device__ __forceinline__ float warpsum(float v) {
    #pragma unroll
    for (int o = 16; o > 0; o >>= 1) v += __shfl_xor_sync(0xffffffffu, v, o);
    return v;
}
__device__ __forceinline__ float warpmax(float v) {
    #pragma unroll
    for (int o = 16; o > 0; o >>= 1) v = fmaxf(v, __shfl_xor_sync(0xffffffffu, v, o));
    return v;
}
__device__ __forceinline__ float sigf(float x) { return 1.0f / (1.0f + expf(-x)); }

// ------------------------- one-time pack / init -------------------------
__global__ void pack_kernel(const float* __restrict__ Uw,
                            const float* __restrict__ Wih_f, const float* __restrict__ Whh_f,
                            const float* __restrict__ b_f,
                            const float* __restrict__ Wih_b, const float* __restrict__ Whh_b,
                            const float* __restrict__ b_b,
                            const float* __restrict__ h0, const float* __restrict__ c0) {
    const size_t NTOT = (size_t)2 * H4 * H4;  // 2,097,152
    for (size_t idx = (size_t)blockIdx.x * blockDim.x + threadIdx.x; idx < NTOT;
         idx += (size_t)gridDim.x * blockDim.x) {
        size_t d = idx >> 20;
        size_t r = (idx >> 10) & 1023;
        size_t k = idx & 1023;
        const float* Wih = d ? Wih_b : Wih_f;
        const float* Whh = d ? Whh_b : Whh_f;
        g_Wcat[idx] = (k < H3) ? Wih[r * H3 + k] : Whh[r * H + (k - H3)];

        if (idx < (size_t)H2 * H) {
            size_t j = idx >> 8, kk = idx & 255;
            g_UwS[idx] = Uw[j * H2 + kk] + Uw[j * H2 + H + kk];
        }
        if (idx < 2 * H4) g_bcat[idx] = (idx < H4) ? b_f[idx] : b_b[idx - H4];
        if (idx < 2 * B * H) { g_h[idx] = h0[idx]; g_c[idx] = c0[idx]; }
        if (idx < B) g_x[idx] = 0;
    }
}

// ------------------------- double-buffered fp32 GEMM: C = A @ W.T + bias -------------------------
// A:[M,K] row-major, W:[N,K] row-major, C row stride ldC. Dims divide tile sizes.
// blockIdx.z batches (zA/zW/zB/zC strides). ksplit>1: blockIdx.y = k-slice (M<=64),
// each slice writes its partial into C + ks*zCk; bias added only in slice 0.
#define GBM 64
#define GBN 128
#define GBK 32
__global__ void __launch_bounds__(256) gemm_abt(
    const float* __restrict__ A, const float* __restrict__ W,
    const float* __restrict__ bias, float* __restrict__ C,
    int M, int N, int K, int ldC,
    size_t zA, size_t zW, size_t zB, size_t zC,
    int ksplit, size_t zCk) {
    A += (size_t)blockIdx.z * zA;
    W += (size_t)blockIdx.z * zW;
    bias += (size_t)blockIdx.z * zB;
    C += (size_t)blockIdx.z * zC;

    int mb, ks;
    if (ksplit > 1) { mb = 0; ks = blockIdx.y; } else { mb = blockIdx.y; ks = 0; }
    const int kLen = K / ksplit;
    const int kBegin = ks * kLen;
    C += (size_t)ks * zCk;

    __shared__ float As[2][GBK][GBM];   // 16 KB
    __shared__ float Bs[2][GBK][GBN];   // 32 KB

    const int tid = threadIdx.x;
    const int tx = tid & 15, ty = tid >> 4;     // 16 x 16 threads
    const int mBase = mb * GBM;
    const int nBase = blockIdx.x * GBN;

    // load assignments (fixed per thread)
    const int ar0 = (tid) >> 3,        akq0 = tid & 7;
    const int ar1 = (tid + 256) >> 3,  akq1 = tid & 7;   // (tid+256)&7 == tid&7
    float acc[4][8];
    #pragma unroll
    for (int i = 0; i < 4; i++)
        #pragma unroll
        for (int j = 0; j < 8; j++) acc[i][j] = 0.0f;

    float4 ra[2], rb[4];

    #define LOAD_TILE(k0)                                                                 \
        do {                                                                              \
            ra[0] = *reinterpret_cast<const float4*>(&A[(size_t)(mBase + ar0) * K + (k0) + akq0 * 4]); \
            ra[1] = *reinterpret_cast<const float4*>(&A[(size_t)(mBase + ar1) * K + (k0) + akq1 * 4]); \
            _Pragma("unroll")                                                             \
            for (int i = 0; i < 4; i++) {                                                 \
                int f4 = tid + 256 * i; int r = f4 >> 3, kq = f4 & 7;                     \
                rb[i] = *reinterpret_cast<const float4*>(&W[(size_t)(nBase + r) * K + (k0) + kq * 4]); \
            }                                                                             \
        } while (0)

    #define STORE_TILE(bi)                                                                \
        do {                                                                              \
            As[bi][akq0 * 4 + 0][ar0] = ra[0].x; As[bi][akq0 * 4 + 1][ar0] = ra[0].y;     \
            As[bi][akq0 * 4 + 2][ar0] = ra[0].z; As[bi][akq0 * 4 + 3][ar0] = ra[0].w;     \
            As[bi][akq1 * 4 + 0][ar1] = ra[1].x; As[bi][akq1 * 4 + 1][ar1] = ra[1].y;     \
            As[bi][akq1 * 4 + 2][ar1] = ra[1].z; As[bi][akq1 * 4 + 3][ar1] = ra[1].w;     \
            _Pragma("unroll")                                                             \
            for (int i = 0; i < 4; i++) {                                                 \
                int f4 = tid + 256 * i; int r = f4 >> 3, kq = f4 & 7;                     \
                Bs[bi][kq * 4 + 0][r] = rb[i].x; Bs[bi][kq * 4 + 1][r] = rb[i].y;         \
                Bs[bi][kq * 4 + 2][r] = rb[i].z; Bs[bi][kq * 4 + 3][r] = rb[i].w;         \
            }                                                                             \
        } while (0)

    #define COMPUTE(bi)                                                                   \
        do {                                                                              \
            _Pragma("unroll")                                                             \
            for (int k = 0; k < GBK; k++) {                                               \
                float4 a4 = *reinterpret_cast<const float4*>(&As[bi][k][ty * 4]);         \
                float4 b0 = *reinterpret_cast<const float4*>(&Bs[bi][k][tx * 8]);         \
                float4 b1 = *reinterpret_cast<const float4*>(&Bs[bi][k][tx * 8 + 4]);     \
                float a[4] = {a4.x, a4.y, a4.z, a4.w};                                    \
                float b[8] = {b0.x, b0.y, b0.z, b0.w, b1.x, b1.y, b1.z, b1.w};            \
                _Pragma("unroll")                                                         \
                for (int i = 0; i < 4; i++)                                               \
                    _Pragma("unroll")                                                     \
                    for (int j = 0; j < 8; j++) acc[i][j] = fmaf(a[i], b[j], acc[i][j]);  \
            }                                                                             \
        } while (0)

    const int nIter = kLen / GBK;
    LOAD_TILE(kBegin);
    STORE_TILE(0);
    __syncthreads();
    int buf = 0;
    for (int it = 1; it < nIter; it++) {
        LOAD_TILE(kBegin + it * GBK);   // prefetch next tile into regs
        COMPUTE(buf);                    // compute current
        STORE_TILE(buf ^ 1);             // stage into other buffer
        __syncthreads();
        buf ^= 1;
    }
    COMPUTE(buf);

    #pragma unroll
    for (int i = 0; i < 4; i++) {
        size_t row = (size_t)(mBase + ty * 4 + i);
        #pragma unroll
        for (int j = 0; j < 8; j++) {
            int col = nBase + tx * 8 + j;
            float bj = (ks == 0) ? bias[col] : 0.0f;
            C[row * (size_t)ldC + col] = acc[i][j] + bj;
        }
    }
    #undef LOAD_TILE
    #undef STORE_TILE
    #undef COMPUTE
}

// ------------------------- attention, stage 1: qU = h_f @ UwS.T + Ub -------------------------
// grid (8, B): block x-slice covers 64 j's
__global__ void __launch_bounds__(256) attn_qU_kernel(const float* __restrict__ Ub) {
    __shared__ float h_s[H];
    int b = blockIdx.y, tid = threadIdx.x;
    int j0 = blockIdx.x * 64;
    if (tid < H) h_s[tid] = g_h[(size_t)b * H + tid];   // forward dir (d=0)
    __syncthreads();
    int warp = tid >> 5, lane = tid & 31;
    #pragma unroll
    for (int jj = 0; jj < 8; jj++) {
        int j = j0 + warp * 8 + jj;
        const float* u = g_UwS + (size_t)j * H;
        float s = 0.0f;
        #pragma unroll
        for (int k = lane; k < H; k += 32) s += u[k] * h_s[k];
        s = warpsum(s);
        if (lane == 0) g_qU[(size_t)b * H2 + j] = s + Ub[j];
    }
}

// ------------------------- attention, stage 2: scores -------------------------
// grid (8, B): block covers 16 s-positions; score = Vw . tanh(qU + encp) + Vb
__global__ void __launch_bounds__(256) attn_score_kernel(const float* __restrict__ Vw,
                                                         const float* __restrict__ Vb) {
    __shared__ float qs[H2], vs[H2];
    int b = blockIdx.y, tid = threadIdx.x;
    for (int j = tid; j < H2; j += 256) { qs[j] = g_qU[(size_t)b * H2 + j]; vs[j] = Vw[j]; }
    __syncthreads();
    int warp = tid >> 5, lane = tid & 31;
    float vb = Vb[0];
    #pragma unroll
    for (int i = 0; i < 2; i++) {
        int s = blockIdx.x * 16 + i * 8 + warp;
        const float* ep = g_encp + ((size_t)b * S + s) * H2;
        float acc = 0.0f;
        #pragma unroll 4
        for (int j = lane; j < H2; j += 32) acc += vs[j] * tanhf(qs[j] + ep[j]);
        acc = warpsum(acc);
        if (lane == 0) g_score[(size_t)b * S + s] = acc + vb;
    }
}

// ------------------------- attention, stage 3: softmax (redundant per block) + context -------------------------
// grid (4, B), 128 threads: block covers 128 d's of ctx
__global__ void __launch_bounds__(128) attn_ctx_kernel(const float* __restrict__ enc) {
    __shared__ float w[S];
    __shared__ float redm[4], reds[4];
    int b = blockIdx.y, tid = threadIdx.x;
    int warp = tid >> 5, lane = tid & 31;

    float sc = g_score[(size_t)b * S + tid];
    float m = warpmax(sc);
    if (lane == 0) redm[warp] = m;
    __syncthreads();
    float mx = fmaxf(fmaxf(redm[0], redm[1]), fmaxf(redm[2], redm[3]));
    float e = expf(sc - mx);
    float su = warpsum(e);
    if (lane == 0) reds[warp] = su;
    __syncthreads();
    float inv = 1.0f / (reds[0] + reds[1] + reds[2] + reds[3]);
    w[tid] = e * inv;
    __syncthreads();

    int d = blockIdx.x * 128 + tid;
    const float* eb = enc + (size_t)b * S * H2 + d;
    float acc = 0.0f;
    #pragma unroll 8
    for (int s = 0; s < S; s++) acc += w[s] * eb[(size_t)s * H2];
    g_ctx[(size_t)b * H2 + d] = acc;
}

// ------------------------- LSTM input gather -------------------------
__global__ void build_xin_kernel(const float* __restrict__ embt) {
    int idx = blockIdx.x * blockDim.x + threadIdx.x;   // < 2*64*1024
    if (idx >= 2 * B * H4) return;
    int d = idx >> 16;
    int b = (idx >> 10) & (B - 1);
    int k = idx & (H4 - 1);
    float v;
    if (k < H2)       v = g_ctx[b * H2 + k];
    else if (k < H3)  v = embt[(size_t)g_x[b] * H + (k - H2)];
    else              v = g_h[(d * B + b) * H + (k - H3)];
    g_xin[idx] = v;
}

// ------------------------- LSTM activation (sums split-K partials) -------------------------
__global__ void lstm_act_kernel() {
    int idx = blockIdx.x * blockDim.x + threadIdx.x;   // < 2*64*256
    if (idx >= 2 * B * H) return;
    int d = idx / (B * H);
    int b = (idx / H) % B;
    int k = idx % H;
    size_t base = ((size_t)d * B + b) * H4;
    float gi = 0, gf = 0, gg = 0, go = 0;
    #pragma unroll
    for (int s = 0; s < KSPLIT_G; s++) {
        const float* Gp = g_Gp + (size_t)s * 2 * B * H4 + base;
        gi += Gp[k]; gf += Gp[H + k]; gg += Gp[2 * H + k]; go += Gp[3 * H + k];
    }
    float c_old = g_c[idx];
    float c2 = sigf(gf) * c_old + sigf(gi) * tanhf(gg);
    float h2 = sigf(go) * tanhf(c2);
    g_c[idx] = c2;
    g_h[idx] = h2;
    g_out[(size_t)b * H2 + d * H + k] = h2;
}

// ------------------------- argmax (first-index tie-break) -------------------------
__global__ void argmax_kernel(const float* __restrict__ yt) {
    int b = blockIdx.x, tid = threadIdx.x;
    const float* row = yt + (size_t)b * T * V;
    float best = -INFINITY; int bi = 0x7fffffff;
    for (int v = tid; v < V; v += 256) {
        float val = row[v];
        if (val > best) { best = val; bi = v; }   // strided ascending -> first-idx on ties
    }
    __shared__ float bv[256];
    __shared__ int   bx[256];
    bv[tid] = best; bx[tid] = bi;
    __syncthreads();
    for (int st = 128; st > 0; st >>= 1) {
        if (tid < st) {
            if (bv[tid + st] > bv[tid] ||
                (bv[tid + st] == bv[tid] && bx[tid + st] < bx[tid])) {
                bv[tid] = bv[tid + st]; bx[tid] = bx[tid + st];
            }
        }
        __syncthreads();
    }
    if (tid == 0) g_x[b] = bx[0];
}

// ------------------------- tail: hT, cT -------------------------
__global__ void tail_kernel(float* __restrict__ out) {
    int idx = blockIdx.x * blockDim.x + threadIdx.x;
    if (idx < 2 * B * H) {
        out[(size_t)B * T * V + idx] = g_h[idx];
        out[(size_t)B * T * V + 2 * B * H + idx] = g_c[idx];
    }
}

// ------------------------- host -------------------------
extern "C" void kernel_launch(void* const* d_in, const int* in_sizes, int n_in,
                              void* d_out, int out_size) {
    const float* enc   = (const float*)d_in[0];
    const float* h0    = (const float*)d_in[1];
    const float* c0    = (const float*)d_in[2];
    const float* Uw    = (const float*)d_in[3];
    const float* Ub    = (const float*)d_in[4];
    const float* Ww    = (const float*)d_in[5];
    const float* Wb    = (const float*)d_in[6];
    const float* Vw    = (const float*)d_in[7];
    const float* Vb    = (const float*)d_in[8];
    const float* Wih_f = (const float*)d_in[9];
    const float* Whh_f = (const float*)d_in[10];
    const float* b_f   = (const float*)d_in[11];
    const float* Wih_b = (const float*)d_in[12];
    const float* Whh_b = (const float*)d_in[13];
    const float* b_b   = (const float*)d_in[14];
    const float* Fw    = (const float*)d_in[15];
    const float* Fb    = (const float*)d_in[16];
    const float* embt  = (const float*)d_in[17];
    (void)in_sizes; (void)n_in;
    float* out = (float*)d_out;

    // one-time packing + state init
    pack_kernel<<<2048, 1024>>>(Uw, Wih_f, Whh_f, b_f, Wih_b, Whh_b, b_b, h0, c0);

    // enc_proj = enc @ Ww.T + Wb   (M=8192, N=512, K=512)
    {
        float* encp;  cudaGetSymbolAddress((void**)&encp, g_encp);
        gemm_abt<<<dim3(H2 / GBN, (B * S) / GBM, 1), 256>>>(
            enc, Ww, Wb, encp, B * S, H2, H2, H2, 0, 0, 0, 0, 1, 0);
    }

    float *xin, *Wcat, *bcat, *Gp, *outbuf;
    cudaGetSymbolAddress((void**)&xin,   g_xin);
    cudaGetSymbolAddress((void**)&Wcat,  g_Wcat);
    cudaGetSymbolAddress((void**)&bcat,  g_bcat);
    cudaGetSymbolAddress((void**)&Gp,    g_Gp);
    cudaGetSymbolAddress((void**)&outbuf, g_out);

    for (int t = 0; t < T; t++) {
        attn_qU_kernel<<<dim3(8, B), 256>>>(Ub);
        attn_score_kernel<<<dim3(8, B), 256>>>(Vw, Vb);
        attn_ctx_kernel<<<dim3(4, B), 128>>>(enc);
        build_xin_kernel<<<(2 * B * H4) / 256, 256>>>(embt);
        // gates: xin_d @ Wcat_d.T + b_d, split-K x8, dirs via z
        gemm_abt<<<dim3(H4 / GBN, KSPLIT_G, 2), 256>>>(
            xin, Wcat, bcat, Gp, B, H4, H4, H4,
            (size_t)B * H4, (size_t)H4 * H4, (size_t)H4, (size_t)B * H4,
            KSPLIT_G, (size_t)2 * B * H4);
        lstm_act_kernel<<<(2 * B * H) / 256, 256>>>();
        // logits: out @ Fw.T + Fb, written directly into ys[:, t, :]
        gemm_abt<<<dim3(V / GBN, 1, 1), 256>>>(
            outbuf, Fw, Fb, out + (size_t)t * V, B, V, H2, T * V,
            0, 0, 0, 0, 1, 0);
        argmax_kernel<<<B, 256>>>(out + (size_t)t * V);
    }

    if (out_size >= B * T * V + 4 * B * H)
        tail_kernel<<<(2 * B * H + 255) / 256, 256>>>(out);
}

// round 6
// speedup vs baseline: 2.7777x; 1.9836x over previous
#include <cuda_runtime.h>
#include <cuda_bf16.h>
#include <math.h>
#include <stdint.h>

// Problem dims (fixed)
#define B   64
#define S   128
#define H   256
#define H2  512
#define H3  768
#define H4  1024
#define V   32000
#define T   32

#define KSPLIT_G 8   // gates GEMM k-split

// ------------------------- scratch (static device globals) -------------------------
__device__ float g_encp[B * S * H2];          // enc @ Ww.T + Wb   (16.8 MB)
__device__ float g_UwS[H2 * H];               // Uw[:, :H] + Uw[:, H:]
__device__ float g_qU[B * H2];                // h_f @ UwS.T + Ub
__device__ float g_score[B * S];              // raw attention scores
__device__ float g_ctx[B * H2];               // attention context
__device__ float g_xin[2 * B * H4];           // [ctx, emb, h_d] per direction
__device__ float g_Wcat[2 * H4 * H4];         // [Wih | Whh] per direction (8 MB)
__device__ float g_bcat[2 * H4];
__device__ float g_Gp[KSPLIT_G * 2 * B * H4]; // split-K partial gate sums (4 MB)
__device__ float g_h[2 * B * H];
__device__ float g_c[2 * B * H];
__device__ int   g_x[B];                      // greedy token feedback
// bf16x3 split operands for the vocab GEMM
__device__ __nv_bfloat16 g_Fw_hi[(size_t)V * H2];   // 32.8 MB
__device__ __nv_bfloat16 g_Fw_lo[(size_t)V * H2];   // 32.8 MB
__device__ __nv_bfloat16 g_out_hi[B * H2];
__device__ __nv_bfloat16 g_out_lo[B * H2];

__device__ __forceinline__ float warpsum(float v) {
    #pragma unroll
    for (int o = 16; o > 0; o >>= 1) v += __shfl_xor_sync(0xffffffffu, v, o);
    return v;
}
__device__ __forceinline__ float warpmax(float v) {
    #pragma unroll
    for (int o = 16; o > 0; o >>= 1) v = fmaxf(v, __shfl_xor_sync(0xffffffffu, v, o));
    return v;
}
__device__ __forceinline__ float sigf(float x) { return 1.0f / (1.0f + expf(-x)); }

// ------------------------- portable PTX helpers (sm_80+ baseline, no 'a'-target) ---
__device__ __forceinline__ uint32_t smem_u32(const void* p) {
    uint32_t a;
    asm("{ .reg .u64 t; cvta.to.shared.u64 t, %1; cvt.u32.u64 %0, t; }" : "=r"(a) : "l"(p));
    return a;
}
#define SWZ(x) ((x) ^ (((x) >> 3) & 0x70))

#define CP16(saddr, gptr) \
    asm volatile("cp.async.cg.shared.global [%0], [%1], 16;" :: "r"(saddr), "l"(gptr))
#define CP_COMMIT() asm volatile("cp.async.commit_group;" ::: "memory")
#define CP_WAIT(n)  asm volatile("cp.async.wait_group %0;" :: "n"(n) : "memory")

__device__ __forceinline__ void ldsm4(uint32_t* r, uint32_t addr) {
    asm volatile("ldmatrix.sync.aligned.m8n8.x4.shared.b16 {%0,%1,%2,%3}, [%4];"
        : "=r"(r[0]), "=r"(r[1]), "=r"(r[2]), "=r"(r[3]) : "r"(addr));
}
__device__ __forceinline__ void mma16816(float* c, const uint32_t* a, const uint32_t* b) {
    asm volatile("mma.sync.aligned.m16n8k16.row.col.f32.bf16.bf16.f32 "
        "{%0,%1,%2,%3}, {%4,%5,%6,%7}, {%8,%9}, {%0,%1,%2,%3};"
        : "+f"(c[0]), "+f"(c[1]), "+f"(c[2]), "+f"(c[3])
        : "r"(a[0]), "r"(a[1]), "r"(a[2]), "r"(a[3]), "r"(b[0]), "r"(b[1]));
}

// ------------------------- one-time pack / init -------------------------
__global__ void pack_kernel(const float* __restrict__ Uw,
                            const float* __restrict__ Wih_f, const float* __restrict__ Whh_f,
                            const float* __restrict__ b_f,
                            const float* __restrict__ Wih_b, const float* __restrict__ Whh_b,
                            const float* __restrict__ b_b,
                            const float* __restrict__ h0, const float* __restrict__ c0) {
    const size_t NTOT = (size_t)2 * H4 * H4;  // 2,097,152
    for (size_t idx = (size_t)blockIdx.x * blockDim.x + threadIdx.x; idx < NTOT;
         idx += (size_t)gridDim.x * blockDim.x) {
        size_t d = idx >> 20;
        size_t r = (idx >> 10) & 1023;
        size_t k = idx & 1023;
        const float* Wih = d ? Wih_b : Wih_f;
        const float* Whh = d ? Whh_b : Whh_f;
        g_Wcat[idx] = (k < H3) ? Wih[r * H3 + k] : Whh[r * H + (k - H3)];

        if (idx < (size_t)H2 * H) {
            size_t j = idx >> 8, kk = idx & 255;
            g_UwS[idx] = Uw[j * H2 + kk] + Uw[j * H2 + H + kk];
        }
        if (idx < 2 * H4) g_bcat[idx] = (idx < H4) ? b_f[idx] : b_b[idx - H4];
        if (idx < 2 * B * H) { g_h[idx] = h0[idx]; g_c[idx] = c0[idx]; }
        if (idx < B) g_x[idx] = 0;
    }
}

// split Fw into hi/lo bf16 once
__global__ void pack_fw_kernel(const float* __restrict__ Fw) {
    const size_t NTOT = (size_t)V * H2;
    for (size_t i = (size_t)blockIdx.x * blockDim.x + threadIdx.x; i < NTOT;
         i += (size_t)gridDim.x * blockDim.x) {
        float v = Fw[i];
        __nv_bfloat16 hi = __float2bfloat16(v);
        g_Fw_hi[i] = hi;
        g_Fw_lo[i] = __float2bfloat16(v - __bfloat162float(hi));
    }
}

// ------------------------- double-buffered fp32 GEMM: C = A @ W.T + bias -------------------------
#define GBM 64
#define GBN 128
#define GBK 32
__global__ void __launch_bounds__(256) gemm_abt(
    const float* __restrict__ A, const float* __restrict__ W,
    const float* __restrict__ bias, float* __restrict__ C,
    int M, int N, int K, int ldC,
    size_t zA, size_t zW, size_t zB, size_t zC,
    int ksplit, size_t zCk) {
    A += (size_t)blockIdx.z * zA;
    W += (size_t)blockIdx.z * zW;
    bias += (size_t)blockIdx.z * zB;
    C += (size_t)blockIdx.z * zC;

    int mb, ks;
    if (ksplit > 1) { mb = 0; ks = blockIdx.y; } else { mb = blockIdx.y; ks = 0; }
    const int kLen = K / ksplit;
    const int kBegin = ks * kLen;
    C += (size_t)ks * zCk;

    __shared__ float As[2][GBK][GBM];
    __shared__ float Bs[2][GBK][GBN];

    const int tid = threadIdx.x;
    const int tx = tid & 15, ty = tid >> 4;
    const int mBase = mb * GBM;
    const int nBase = blockIdx.x * GBN;

    const int ar0 = (tid) >> 3,        akq0 = tid & 7;
    const int ar1 = (tid + 256) >> 3,  akq1 = tid & 7;
    float acc[4][8];
    #pragma unroll
    for (int i = 0; i < 4; i++)
        #pragma unroll
        for (int j = 0; j < 8; j++) acc[i][j] = 0.0f;

    float4 ra[2], rb[4];

    #define LOAD_TILE(k0)                                                                 \
        do {                                                                              \
            ra[0] = *reinterpret_cast<const float4*>(&A[(size_t)(mBase + ar0) * K + (k0) + akq0 * 4]); \
            ra[1] = *reinterpret_cast<const float4*>(&A[(size_t)(mBase + ar1) * K + (k0) + akq1 * 4]); \
            _Pragma("unroll")                                                             \
            for (int i = 0; i < 4; i++) {                                                 \
                int f4 = tid + 256 * i; int r = f4 >> 3, kq = f4 & 7;                     \
                rb[i] = *reinterpret_cast<const float4*>(&W[(size_t)(nBase + r) * K + (k0) + kq * 4]); \
            }                                                                             \
        } while (0)

    #define STORE_TILE(bi)                                                                \
        do {                                                                              \
            As[bi][akq0 * 4 + 0][ar0] = ra[0].x; As[bi][akq0 * 4 + 1][ar0] = ra[0].y;     \
            As[bi][akq0 * 4 + 2][ar0] = ra[0].z; As[bi][akq0 * 4 + 3][ar0] = ra[0].w;     \
            As[bi][akq1 * 4 + 0][ar1] = ra[1].x; As[bi][akq1 * 4 + 1][ar1] = ra[1].y;     \
            As[bi][akq1 * 4 + 2][ar1] = ra[1].z; As[bi][akq1 * 4 + 3][ar1] = ra[1].w;     \
            _Pragma("unroll")                                                             \
            for (int i = 0; i < 4; i++) {                                                 \
                int f4 = tid + 256 * i; int r = f4 >> 3, kq = f4 & 7;                     \
                Bs[bi][kq * 4 + 0][r] = rb[i].x; Bs[bi][kq * 4 + 1][r] = rb[i].y;         \
                Bs[bi][kq * 4 + 2][r] = rb[i].z; Bs[bi][kq * 4 + 3][r] = rb[i].w;         \
            }                                                                             \
        } while (0)

    #define COMPUTE(bi)                                                                   \
        do {                                                                              \
            _Pragma("unroll")                                                             \
            for (int k = 0; k < GBK; k++) {                                               \
                float4 a4 = *reinterpret_cast<const float4*>(&As[bi][k][ty * 4]);         \
                float4 b0 = *reinterpret_cast<const float4*>(&Bs[bi][k][tx * 8]);         \
                float4 b1 = *reinterpret_cast<const float4*>(&Bs[bi][k][tx * 8 + 4]);     \
                float a[4] = {a4.x, a4.y, a4.z, a4.w};                                    \
                float b[8] = {b0.x, b0.y, b0.z, b0.w, b1.x, b1.y, b1.z, b1.w};            \
                _Pragma("unroll")                                                         \
                for (int i = 0; i < 4; i++)                                               \
                    _Pragma("unroll")                                                     \
                    for (int j = 0; j < 8; j++) acc[i][j] = fmaf(a[i], b[j], acc[i][j]);  \
            }                                                                             \
        } while (0)

    const int nIter = kLen / GBK;
    LOAD_TILE(kBegin);
    STORE_TILE(0);
    __syncthreads();
    int buf = 0;
    for (int it = 1; it < nIter; it++) {
        LOAD_TILE(kBegin + it * GBK);
        COMPUTE(buf);
        STORE_TILE(buf ^ 1);
        __syncthreads();
        buf ^= 1;
    }
    COMPUTE(buf);

    #pragma unroll
    for (int i = 0; i < 4; i++) {
        size_t row = (size_t)(mBase + ty * 4 + i);
        #pragma unroll
        for (int j = 0; j < 8; j++) {
            int col = nBase + tx * 8 + j;
            float bj = (ks == 0) ? bias[col] : 0.0f;
            C[row * (size_t)ldC + col] = acc[i][j] + bj;
        }
    }
    #undef LOAD_TILE
    #undef STORE_TILE
    #undef COMPUTE
}

// ------------------------- vocab GEMM: mma.sync bf16x3, y[b, v0+m] -------------------------
// Per CTA: M=128 vocab rows, N=64 batch, K=512 in 8 cp.async chunks of 64.
// SMEM (1024-aligned base):
//   A_HI[2] @ 0      (2 x 16 KB: 128 rows x 128B, SWZ)
//   A_LO[2] @ 32768
//   B_HI[2] @ 65536  (2 x 8 KB: 64 rows x 128B, SWZ)   rows = batch (out[b][k])
//   B_LO[2] @ 81920
#define VSM_DYN (98304 + 1024)

__device__ __forceinline__ void vissue_chunk(uint32_t tb, int v0, int c, int buf, int tid) {
    const uint32_t AHI = tb + buf * 16384u, ALO = tb + 32768u + buf * 16384u;
    const uint32_t BHI = tb + 65536u + buf * 8192u, BLO = tb + 81920u + buf * 8192u;
    #pragma unroll
    for (int i = 0; i < 4; i++) {
        int idx = tid + 256 * i;
        int r = idx >> 3, q = idx & 7;
        size_t g = (size_t)(v0 + r) * H2 + c * 64 + q * 8;
        uint32_t so = SWZ((uint32_t)(r * 128 + q * 16));
        CP16(AHI + so, (const char*)(g_Fw_hi + g));
        CP16(ALO + so, (const char*)(g_Fw_lo + g));
    }
    #pragma unroll
    for (int i = 0; i < 2; i++) {
        int idx = tid + 256 * i;
        int r = idx >> 3, q = idx & 7;
        size_t g = (size_t)r * H2 + c * 64 + q * 8;
        uint32_t so = SWZ((uint32_t)(r * 128 + q * 16));
        CP16(BHI + so, (const char*)(g_out_hi + g));
        CP16(BLO + so, (const char*)(g_out_lo + g));
    }
    CP_COMMIT();
}

__global__ void __launch_bounds__(256, 2) vocab_kernel(const float* __restrict__ Fb,
                                                       float* __restrict__ yt) {
    extern __shared__ char dsm[];
    uint32_t sb0 = smem_u32(dsm);
    uint32_t tb = (sb0 + 1023) & ~1023u;            // 1024-aligned tile base
    char* base = dsm + (tb - sb0);

    const int tid = threadIdx.x;
    const int wid = tid >> 5, lane = tid & 31;
    const int v0 = blockIdx.x * 128;
    const int wm = wid * 16;                        // warp's m offset (vocab rows)

    // ldmatrix source addresses (fixed per thread, per buffer, per product half)
    // A frag (16x16): mats [m0-7,k0-7],[m8-15,k0-7],[m0-7,k8-15],[m8-15,k8-15]
    const int a_row = wm + (lane & 7) + ((lane >> 3) & 1) * 8;
    const int a_kb  = (lane >> 4) * 16;             // byte offset of k-sub (0 or 16B)
    // B frags x4 -> 2 n-tiles: mats [n0-7,k0-7],[n0-7,k8-15],[n8-15,k0-7],[n8-15,k8-15]
    const int b_rowi = (lane & 7) + (lane >> 4) * 8;   // + p*16 for pair p
    const int b_kb  = ((lane >> 3) & 1) * 16;

    float acc[8][4];
    #pragma unroll
    for (int i = 0; i < 8; i++)
        #pragma unroll
        for (int j = 0; j < 4; j++) acc[i][j] = 0.0f;

    vissue_chunk(tb, v0, 0, 0, tid);
    vissue_chunk(tb, v0, 1, 1, tid);

    for (int c = 0; c < 8; c++) {
        const int buf = c & 1;
        // groups issued so far = min(c+2, 8); chunk c must be complete:
        // allowed in-flight = issued - (c+1) = 1 for c<=6, 0 for c==7.
        if (c < 7) { CP_WAIT(1); } else { CP_WAIT(0); }
        __syncthreads();

        const uint32_t AHI = tb + buf * 16384u, ALO = tb + 32768u + buf * 16384u;
        const uint32_t BHI = tb + 65536u + buf * 8192u, BLO = tb + 81920u + buf * 8192u;

        #pragma unroll
        for (int ks = 0; ks < 4; ks++) {
            uint32_t ah[4], al[4];
            uint32_t aoff = SWZ((uint32_t)(a_row * 128 + ks * 32 + a_kb));
            ldsm4(ah, AHI + aoff);
            ldsm4(al, ALO + aoff);
            #pragma unroll
            for (int p = 0; p < 4; p++) {
                uint32_t bh[4], bl[4];
                uint32_t boff = SWZ((uint32_t)((b_rowi + p * 16) * 128 + ks * 32 + b_kb));
                ldsm4(bh, BHI + boff);
                ldsm4(bl, BLO + boff);
                mma16816(acc[2 * p],     ah, bh);
                mma16816(acc[2 * p],     al, bh);
                mma16816(acc[2 * p],     ah, bl);
                mma16816(acc[2 * p + 1], ah, bh + 2);
                mma16816(acc[2 * p + 1], al, bh + 2);
                mma16816(acc[2 * p + 1], ah, bl + 2);
            }
        }
        __syncthreads();      // all warps done with buf before it is overwritten
        if (c < 6) vissue_chunk(tb, v0, c + 2, buf, tid);
    }

    // epilogue: transpose via smem -> coalesced global store with bias
    float* tr = (float*)base;   // [64 batch][132] floats = 33.8 KB
    {
        const int m0 = wm + (lane >> 2);
        const int nb = 2 * (lane & 3);
        #pragma unroll
        for (int nt = 0; nt < 8; nt++) {
            int n = nt * 8 + nb;
            tr[n * 132 + m0]           = acc[nt][0];
            tr[(n + 1) * 132 + m0]     = acc[nt][1];
            tr[n * 132 + m0 + 8]       = acc[nt][2];
            tr[(n + 1) * 132 + m0 + 8] = acc[nt][3];
        }
    }
    __syncthreads();
    // 64 batches x 32 float4 = 2048 stores over 256 threads -> 8 iterations
    #pragma unroll
    for (int i = 0; i < 8; i++) {
        int q = tid + 256 * i;
        int b = q >> 5, j = q & 31;
        float4 fb4 = *reinterpret_cast<const float4*>(&Fb[v0 + 4 * j]);
        float4 r;
        r.x = tr[b * 132 + 4 * j + 0] + fb4.x;
        r.y = tr[b * 132 + 4 * j + 1] + fb4.y;
        r.z = tr[b * 132 + 4 * j + 2] + fb4.z;
        r.w = tr[b * 132 + 4 * j + 3] + fb4.w;
        *reinterpret_cast<float4*>(&yt[(size_t)b * T * V + v0 + 4 * j]) = r;
    }
}

// ------------------------- attention, stage 1: qU = h_f @ UwS.T + Ub -------------------------
__global__ void __launch_bounds__(256) attn_qU_kernel(const float* __restrict__ Ub) {
    __shared__ float h_s[H];
    int b = blockIdx.y, tid = threadIdx.x;
    int j0 = blockIdx.x * 64;
    if (tid < H) h_s[tid] = g_h[(size_t)b * H + tid];
    __syncthreads();
    int warp = tid >> 5, lane = tid & 31;
    #pragma unroll
    for (int jj = 0; jj < 8; jj++) {
        int j = j0 + warp * 8 + jj;
        const float* u = g_UwS + (size_t)j * H;
        float s = 0.0f;
        #pragma unroll
        for (int k = lane; k < H; k += 32) s += u[k] * h_s[k];
        s = warpsum(s);
        if (lane == 0) g_qU[(size_t)b * H2 + j] = s + Ub[j];
    }
}

// ------------------------- attention, stage 2: scores -------------------------
__global__ void __launch_bounds__(256) attn_score_kernel(const float* __restrict__ Vw,
                                                         const float* __restrict__ Vb) {
    __shared__ float qs[H2], vs[H2];
    int b = blockIdx.y, tid = threadIdx.x;
    for (int j = tid; j < H2; j += 256) { qs[j] = g_qU[(size_t)b * H2 + j]; vs[j] = Vw[j]; }
    __syncthreads();
    int warp = tid >> 5, lane = tid & 31;
    float vb = Vb[0];
    #pragma unroll
    for (int i = 0; i < 2; i++) {
        int s = blockIdx.x * 16 + i * 8 + warp;
        const float* ep = g_encp + ((size_t)b * S + s) * H2;
        float acc = 0.0f;
        #pragma unroll 4
        for (int j = lane; j < H2; j += 32) acc += vs[j] * tanhf(qs[j] + ep[j]);
        acc = warpsum(acc);
        if (lane == 0) g_score[(size_t)b * S + s] = acc + vb;
    }
}

// ------------------------- attention, stage 3: softmax + context -------------------------
__global__ void __launch_bounds__(128) attn_ctx_kernel(const float* __restrict__ enc) {
    __shared__ float w[S];
    __shared__ float redm[4], reds[4];
    int b = blockIdx.y, tid = threadIdx.x;
    int warp = tid >> 5, lane = tid & 31;

    float sc = g_score[(size_t)b * S + tid];
    float m = warpmax(sc);
    if (lane == 0) redm[warp] = m;
    __syncthreads();
    float mx = fmaxf(fmaxf(redm[0], redm[1]), fmaxf(redm[2], redm[3]));
    float e = expf(sc - mx);
    float su = warpsum(e);
    if (lane == 0) reds[warp] = su;
    __syncthreads();
    float inv = 1.0f / (reds[0] + reds[1] + reds[2] + reds[3]);
    w[tid] = e * inv;
    __syncthreads();

    int d = blockIdx.x * 128 + tid;
    const float* eb = enc + (size_t)b * S * H2 + d;
    float acc = 0.0f;
    #pragma unroll 8
    for (int s = 0; s < S; s++) acc += w[s] * eb[(size_t)s * H2];
    g_ctx[(size_t)b * H2 + d] = acc;
}

// ------------------------- LSTM input gather -------------------------
__global__ void build_xin_kernel(const float* __restrict__ embt) {
    int idx = blockIdx.x * blockDim.x + threadIdx.x;
    if (idx >= 2 * B * H4) return;
    int d = idx >> 16;
    int b = (idx >> 10) & (B - 1);
    int k = idx & (H4 - 1);
    float v;
    if (k < H2)       v = g_ctx[b * H2 + k];
    else if (k < H3)  v = embt[(size_t)g_x[b] * H + (k - H2)];
    else              v = g_h[(d * B + b) * H + (k - H3)];
    g_xin[idx] = v;
}

// ------------------------- LSTM activation (+ hi/lo split of out) -------------------------
__global__ void lstm_act_kernel() {
    int idx = blockIdx.x * blockDim.x + threadIdx.x;
    if (idx >= 2 * B * H) return;
    int d = idx / (B * H);
    int b = (idx / H) % B;
    int k = idx % H;
    size_t base = ((size_t)d * B + b) * H4;
    float gi = 0, gf = 0, gg = 0, go = 0;
    #pragma unroll
    for (int s = 0; s < KSPLIT_G; s++) {
        const float* Gp = g_Gp + (size_t)s * 2 * B * H4 + base;
        gi += Gp[k]; gf += Gp[H + k]; gg += Gp[2 * H + k]; go += Gp[3 * H + k];
    }
    float c_old = g_c[idx];
    float c2 = sigf(gf) * c_old + sigf(gi) * tanhf(gg);
    float h2 = sigf(go) * tanhf(c2);
    g_c[idx] = c2;
    g_h[idx] = h2;
    int o = b * H2 + d * H + k;
    __nv_bfloat16 hi = __float2bfloat16(h2);
    g_out_hi[o] = hi;
    g_out_lo[o] = __float2bfloat16(h2 - __bfloat162float(hi));
}

// ------------------------- argmax (first-index tie-break) -------------------------
__global__ void argmax_kernel(const float* __restrict__ yt) {
    int b = blockIdx.x, tid = threadIdx.x;
    const float* row = yt + (size_t)b * T * V;
    float best = -INFINITY; int bi = 0x7fffffff;
    for (int v = tid; v < V; v += 256) {
        float val = row[v];
        if (val > best) { best = val; bi = v; }
    }
    __shared__ float bv[256];
    __shared__ int   bx[256];
    bv[tid] = best; bx[tid] = bi;
    __syncthreads();
    for (int st = 128; st > 0; st >>= 1) {
        if (tid < st) {
            if (bv[tid + st] > bv[tid] ||
                (bv[tid + st] == bv[tid] && bx[tid + st] < bx[tid])) {
                bv[tid] = bv[tid + st]; bx[tid] = bx[tid + st];
            }
        }
        __syncthreads();
    }
    if (tid == 0) g_x[b] = bx[0];
}

// ------------------------- tail: hT, cT -------------------------
__global__ void tail_kernel(float* __restrict__ out) {
    int idx = blockIdx.x * blockDim.x + threadIdx.x;
    if (idx < 2 * B * H) {
        out[(size_t)B * T * V + idx] = g_h[idx];
        out[(size_t)B * T * V + 2 * B * H + idx] = g_c[idx];
    }
}

// ------------------------- host -------------------------
extern "C" void kernel_launch(void* const* d_in, const int* in_sizes, int n_in,
                              void* d_out, int out_size) {
    const float* enc   = (const float*)d_in[0];
    const float* h0    = (const float*)d_in[1];
    const float* c0    = (const float*)d_in[2];
    const float* Uw    = (const float*)d_in[3];
    const float* Ub    = (const float*)d_in[4];
    const float* Ww    = (const float*)d_in[5];
    const float* Wb    = (const float*)d_in[6];
    const float* Vw    = (const float*)d_in[7];
    const float* Vb    = (const float*)d_in[8];
    const float* Wih_f = (const float*)d_in[9];
    const float* Whh_f = (const float*)d_in[10];
    const float* b_f   = (const float*)d_in[11];
    const float* Wih_b = (const float*)d_in[12];
    const float* Whh_b = (const float*)d_in[13];
    const float* b_b   = (const float*)d_in[14];
    const float* Fw    = (const float*)d_in[15];
    const float* Fb    = (const float*)d_in[16];
    const float* embt  = (const float*)d_in[17];
    (void)in_sizes; (void)n_in;
    float* out = (float*)d_out;

    static bool attr_set = false;
    if (!attr_set) {
        cudaFuncSetAttribute(vocab_kernel, cudaFuncAttributeMaxDynamicSharedMemorySize, VSM_DYN);
        attr_set = true;
    }

    // one-time packing + state init
    pack_kernel<<<2048, 1024>>>(Uw, Wih_f, Whh_f, b_f, Wih_b, Whh_b, b_b, h0, c0);
    pack_fw_kernel<<<4096, 256>>>(Fw);

    // enc_proj = enc @ Ww.T + Wb
    {
        float* encp;  cudaGetSymbolAddress((void**)&encp, g_encp);
        gemm_abt<<<dim3(H2 / GBN, (B * S) / GBM, 1), 256>>>(
            enc, Ww, Wb, encp, B * S, H2, H2, H2, 0, 0, 0, 0, 1, 0);
    }

    float *xin, *Wcat, *bcat, *Gp;
    cudaGetSymbolAddress((void**)&xin,  g_xin);
    cudaGetSymbolAddress((void**)&Wcat, g_Wcat);
    cudaGetSymbolAddress((void**)&bcat, g_bcat);
    cudaGetSymbolAddress((void**)&Gp,   g_Gp);

    for (int t = 0; t < T; t++) {
        attn_qU_kernel<<<dim3(8, B), 256>>>(Ub);
        attn_score_kernel<<<dim3(8, B), 256>>>(Vw, Vb);
        attn_ctx_kernel<<<dim3(4, B), 128>>>(enc);
        build_xin_kernel<<<(2 * B * H4) / 256, 256>>>(embt);
        gemm_abt<<<dim3(H4 / GBN, KSPLIT_G, 2), 256>>>(
            xin, Wcat, bcat, Gp, B, H4, H4, H4,
            (size_t)B * H4, (size_t)H4 * H4, (size_t)H4, (size_t)B * H4,
            KSPLIT_G, (size_t)2 * B * H4);
        lstm_act_kernel<<<(2 * B * H) / 256, 256>>>();
        vocab_kernel<<<V / 128, 256, VSM_DYN>>>(Fb, out + (size_t)t * V);
        argmax_kernel<<<B, 256>>>(out + (size_t)t * V);
    }

    if (out_size >= B * T * V + 4 * B * H)
        tail_kernel<<<(2 * B * H + 255) / 256, 256>>>(out);
}